// round 1
// baseline (speedup 1.0000x reference)
#include <cuda_runtime.h>
#include <cstdint>

// Global flag scratch (no allocations allowed).
// bit0: any(((x+1)+1) >= 3)      -> chain stops after layer 3 (output = x+1+1)
// bit1: any(((((x+1)+1)+1)+1) >= 3) -> chain stops after layer 6 (output = x+4 adds)
__device__ int g_flags;

__global__ void scn_init_kernel() {
    g_flags = 0;
}

// Streaming pass: out = (x+1)+1 speculatively, plus the two global any-reductions.
__global__ void __launch_bounds__(512) scn_main_kernel(
    const float4* __restrict__ x, float4* __restrict__ out, int n4)
{
    int idx = blockIdx.x * blockDim.x + threadIdx.x;
    int stride = gridDim.x * blockDim.x;

    bool a = false;  // any(x2 >= 3)
    bool b = false;  // any(x4 >= 3)

    for (int i = idx; i < n4; i += stride) {
        float4 v = x[i];
        // Sequential adds, matching reference rounding exactly.
        float4 o;
        o.x = (v.x + 1.0f) + 1.0f;
        o.y = (v.y + 1.0f) + 1.0f;
        o.z = (v.z + 1.0f) + 1.0f;
        o.w = (v.w + 1.0f) + 1.0f;

        float m2 = fmaxf(fmaxf(o.x, o.y), fmaxf(o.z, o.w));
        a |= (m2 >= 3.0f);

        float4 q;
        q.x = (o.x + 1.0f) + 1.0f;
        q.y = (o.y + 1.0f) + 1.0f;
        q.z = (o.z + 1.0f) + 1.0f;
        q.w = (o.w + 1.0f) + 1.0f;
        float m4 = fmaxf(fmaxf(q.x, q.y), fmaxf(q.z, q.w));
        b |= (m4 >= 3.0f);

        out[i] = o;
    }

    int any_a = __syncthreads_or(a ? 1 : 0);
    int any_b = __syncthreads_or(b ? 1 : 0);
    if (threadIdx.x == 0) {
        int f = (any_a ? 1 : 0) | (any_b ? 2 : 0);
        if (f) atomicOr(&g_flags, f);
    }
}

// Fixup: if bit0 set, speculative output was correct -> immediate exit.
// Otherwise rewrite with the correct deeper-chain values.
__global__ void __launch_bounds__(512) scn_fixup_kernel(
    const float4* __restrict__ x, float4* __restrict__ out, int n4)
{
    int flags = g_flags;
    if (flags & 1) return;  // out already holds (x+1)+1 — done.

    // Chain continued past layer 3: values become x+4 adds; if bit1 also
    // clear, the final layer adds one more.
    bool five = !(flags & 2);

    int idx = blockIdx.x * blockDim.x + threadIdx.x;
    int stride = gridDim.x * blockDim.x;

    for (int i = idx; i < n4; i += stride) {
        float4 v = x[i];
        float4 o;
        o.x = (((v.x + 1.0f) + 1.0f) + 1.0f) + 1.0f;
        o.y = (((v.y + 1.0f) + 1.0f) + 1.0f) + 1.0f;
        o.z = (((v.z + 1.0f) + 1.0f) + 1.0f) + 1.0f;
        o.w = (((v.w + 1.0f) + 1.0f) + 1.0f) + 1.0f;
        if (five) {
            o.x += 1.0f; o.y += 1.0f; o.z += 1.0f; o.w += 1.0f;
        }
        out[i] = o;
    }
}

extern "C" void kernel_launch(void* const* d_in, const int* in_sizes, int n_in,
                              void* d_out, int out_size)
{
    const float4* x = (const float4*)d_in[0];
    float4* out = (float4*)d_out;
    int n = in_sizes[0];
    int n4 = n >> 2;  // 4096*8192 is divisible by 4

    const int threads = 512;
    const int blocks = 148 * 8;  // grid-stride, ~2 CTAs/SM worth of streaming warps

    scn_init_kernel<<<1, 1>>>();
    scn_main_kernel<<<blocks, threads>>>(x, out, n4);
    scn_fixup_kernel<<<blocks, threads>>>(x, out, n4);
}